// round 3
// baseline (speedup 1.0000x reference)
#include <cuda_runtime.h>

#define BB   64
#define TT   512
#define DH   1024

// ---------------- device scratch (static, allocation-free) ----------------
__device__ float g_Gin_ih[1024 * 16];    // [j][d]
__device__ float g_Gin_hh[1024 * 16];    // [j][d]
__device__ float g_G56t_ih[256 * 16];    // [mp][e]  (transposed)
__device__ float g_G56t_hh[256 * 16];    // [mp][e]
__device__ float g_bias4[4096];          // [j][gate]
__device__ float g_ihg[(size_t)BB * TT * 4096]; // [b][t][j][gate]

typedef unsigned long long u64;

// ---------------- packed f32x2 helpers ------------------------------------
__device__ __forceinline__ u64 pk2(float lo, float hi) {
    u64 r; asm("mov.b64 %0, {%1,%2};" : "=l"(r) : "f"(lo), "f"(hi)); return r;
}
__device__ __forceinline__ void upk2(u64 v, float& lo, float& hi) {
    asm("mov.b64 {%0,%1}, %2;" : "=f"(lo), "=f"(hi) : "l"(v));
}
__device__ __forceinline__ u64 ffma2(u64 a, u64 b, u64 c) {
    u64 d; asm("fma.rn.f32x2 %0, %1, %2, %3;" : "=l"(d) : "l"(a), "l"(b), "l"(c));
    return d;
}
__device__ __forceinline__ u64 fadd2(u64 a, u64 b) {
    u64 d; asm("add.rn.f32x2 %0, %1, %2;" : "=l"(d) : "l"(a), "l"(b));
    return d;
}

// ---------------- fast activations (ex2/rcp approx, ~1e-6 accurate) -------
__device__ __forceinline__ float fexp2(float x) {
    float y; asm("ex2.approx.f32 %0, %1;" : "=f"(y) : "f"(x)); return y;
}
__device__ __forceinline__ float frcp(float x) {
    float y; asm("rcp.approx.f32 %0, %1;" : "=f"(y) : "f"(x)); return y;
}
__device__ __forceinline__ float sigmoidf(float x) {
    return frcp(1.0f + fexp2(-1.4426950408889634f * x));
}
__device__ __forceinline__ float tanhf_(float x) {
    return fmaf(2.0f, frcp(1.0f + fexp2(-2.8853900817779268f * x)), -1.0f);
}

// ---------------- kernel 0: build contraction tables (2 CTAs, 1/path) -----
__global__ void k_build(const float* g1i, const float* g2i, const float* g3i,
                        const float* g5i, const float* g6i,
                        const float* g1h, const float* g2h, const float* g3h,
                        const float* g5h, const float* g6h,
                        const float* bih, const float* bhh)
{
    __shared__ float G12[1024]; // [i][j][c]
    int tid  = threadIdx.x;     // 1024 threads
    int path = blockIdx.x;      // 0 = ih, 1 = hh

    const float* g1 = path ? g1h : g1i;
    const float* g2 = path ? g2h : g2i;
    const float* g3 = path ? g3h : g3i;
    const float* g5 = path ? g5h : g5i;
    const float* g6 = path ? g6h : g6i;
    float* Gin  = path ? g_Gin_hh  : g_Gin_ih;
    float* G56t = path ? g_G56t_hh : g_G56t_ih;

    { // G12[i][j][c] = sum_a g1[i,a] g2[a,j,c]
        int i = tid >> 7, j = (tid >> 4) & 7, c = tid & 15;
        float s = 0.f;
        #pragma unroll
        for (int a = 0; a < 16; a++)
            s = fmaf(g1[i * 16 + a], g2[a * 128 + j * 16 + c], s);
        G12[tid] = s;
    }
    __syncthreads();
    // Gin[(i,j,k)][d] = sum_c G12[i,j,c] g3[c,k,d]
    for (int o = tid; o < 16384; o += 1024) {
        int row = o >> 4, d = o & 15;
        int i = row >> 7, j = (row >> 4) & 7, k = row & 15;
        float s = 0.f;
        #pragma unroll
        for (int c = 0; c < 16; c++)
            s = fmaf(G12[i * 128 + j * 16 + c], g3[c * 256 + k * 16 + d], s);
        Gin[row * 16 + d] = s;
    }
    // G56t[mp][e] = sum_f g5[e,m,f] g6[f,p]
    for (int o = tid; o < 4096; o += 1024) {
        int e = o >> 8, m = (o >> 4) & 15, p = o & 15;
        float s = 0.f;
        #pragma unroll
        for (int f = 0; f < 16; f++)
            s = fmaf(g5[e * 256 + m * 16 + f], g6[f * 16 + p], s);
        G56t[(m * 16 + p) * 16 + e] = s;
    }
    if (path == 0) { // bias reindexed to [j][gate]
        int j = tid;
        float4 v;
        v.x = bih[j]        + bhh[j];
        v.y = bih[1024 + j] + bhh[1024 + j];
        v.z = bih[2048 + j] + bhh[2048 + j];
        v.w = bih[3072 + j] + bhh[3072 + j];
        ((float4*)g_bias4)[j] = v;
    }
}

// ---------------- kernel 1: precompute ih gates for all (b,t) -------------
__global__ void __launch_bounds__(256) k_pre(const float* __restrict__ x,
                                             const float* __restrict__ g4i)
{
    __shared__ float xs[1024];
    __shared__ float pp[16][17];
    __shared__ float ihp[16];
    __shared__ __align__(16) float A[256]; // [n][e]

    int rb  = blockIdx.x;
    int tid = threadIdx.x;

    ((float4*)xs)[tid] = ((const float4*)(x + (size_t)rb * 1024))[tid];
    __syncthreads();

    { // ihp[d] = sum_j xs[j] * Gin_ih[j][d]
        int d = tid & 15, ch = tid >> 4;
        const float* gp = g_Gin_ih + (ch * 64) * 16 + d;
        const float* xp = xs + ch * 64;
        float s = 0.f;
        #pragma unroll
        for (int u = 0; u < 64; u++) s = fmaf(xp[u], gp[u * 16], s);
        pp[ch][d] = s;
    }
    __syncthreads();
    if (tid < 16) {
        float s = 0.f;
        #pragma unroll
        for (int c2 = 0; c2 < 16; c2++) s += pp[c2][tid];
        ihp[tid] = s;
    }
    __syncthreads();
    { // A[n][e] = sum_d ihp[d] * g4_ih[d][n][e]
        int n = tid >> 4, e = tid & 15;
        float s = 0.f;
        #pragma unroll
        for (int d = 0; d < 16; d++)
            s = fmaf(ihp[d], __ldg(g4i + d * 256 + n * 16 + e), s);
        A[tid] = s;
    }
    __syncthreads();

    // stage2 (packed over e-pairs): mp = tid
    u64 Gp[8];
    {
        const u64* gt = (const u64*)(g_G56t_ih + tid * 16);
        #pragma unroll
        for (int i = 0; i < 8; i++) Gp[i] = gt[i];
    }
    float* outp = g_ihg + (size_t)rb * 4096;
    #pragma unroll
    for (int k = 0; k < 4; k++) {
        int j = k * 256 + tid;
        float4 bv = ((const float4*)g_bias4)[j];
        u64 a0 = 0ull, a1 = 0ull, a2 = 0ull, a3 = 0ull;
        const u64* Ar0 = (const u64*)(A + (0 * 4 + k) * 16);
        const u64* Ar1 = (const u64*)(A + (1 * 4 + k) * 16);
        const u64* Ar2 = (const u64*)(A + (2 * 4 + k) * 16);
        const u64* Ar3 = (const u64*)(A + (3 * 4 + k) * 16);
        #pragma unroll
        for (int i = 0; i < 8; i++) {
            a0 = ffma2(Ar0[i], Gp[i], a0);
            a1 = ffma2(Ar1[i], Gp[i], a1);
            a2 = ffma2(Ar2[i], Gp[i], a2);
            a3 = ffma2(Ar3[i], Gp[i], a3);
        }
        float l0, h0, l1, h1, l2, h2, l3, h3;
        upk2(a0, l0, h0); upk2(a1, l1, h1);
        upk2(a2, l2, h2); upk2(a3, l3, h3);
        float4 v;
        v.x = l0 + h0 + bv.x; v.y = l1 + h1 + bv.y;
        v.z = l2 + h2 + bv.z; v.w = l3 + h3 + bv.w;
        ((float4*)outp)[j] = v;
    }
}

// ---------------- kernel 2: recurrence, one CTA per batch element --------
__global__ void __launch_bounds__(1024, 1) k_rec(const float* __restrict__ g4h,
                                                 float* __restrict__ out)
{
    __shared__ float g4sh[4096];                 // [d][n][e]
    __shared__ __align__(16) float Ash[256];     // [n][e]
    __shared__ __align__(8)  float Psh[16];
    __shared__ u64 ppu[32 * 8];                  // [warp][d-pair]

    int tid = threadIdx.x;
    int b   = blockIdx.x;
    const unsigned FULL = 0xffffffffu;

    for (int i = tid; i < 4096; i += 1024) g4sh[i] = g4h[i];

    // ---- phase-1 constants: thread = (chunk of 8 j, d-pair q) ----
    int q     = tid & 7;          // d-pair: d = 2q, 2q+1
    int ch    = tid >> 3;         // j chunk: j = ch*8 + u
    int lbase = (ch & 3) * 8;     // src lane of h[ch*8+u] within this warp
    u64 Grp[8];
    {
        const float* base = g_Gin_hh + (ch * 8) * 16 + 2 * q;
        #pragma unroll
        for (int u = 0; u < 8; u++)
            Grp[u] = *(const u64*)(base + u * 16);
    }
    // ---- stage-2 constants ----
    int mp = tid & 255, nb = tid >> 8;
    u64 Gp[8];
    {
        const u64* gt = (const u64*)(g_G56t_hh + mp * 16);
        #pragma unroll
        for (int i = 0; i < 8; i++) Gp[i] = gt[i];
    }
    int warp = tid >> 5, lane = tid & 31;

    float h = 0.f, c = 0.f;
    const float* ihp_ptr = g_ihg + (size_t)b * TT * 4096 + (size_t)tid * 4;
    float* outb = out + (size_t)b * TT * DH;

    __syncthreads();

    for (int t = 0; t < TT; t++) {
        // issue ih-gate load early; consumed after 3 barriers
        float4 ihg = *(const float4*)(ihp_ptr + (size_t)t * 4096);

        // ---- phase 1 (packed): P[2q,2q+1] partials over 8 j's ----
        u64 part = 0ull;
        #pragma unroll
        for (int u = 0; u < 8; u++) {
            float hu = __shfl_sync(FULL, h, lbase + u, 32);
            part = ffma2(pk2(hu, hu), Grp[u], part);
        }
        part = fadd2(part, __shfl_xor_sync(FULL, part, 8));
        part = fadd2(part, __shfl_xor_sync(FULL, part, 16));
        if (lane < 8) ppu[warp * 8 + q] = part;
        __syncthreads();                               // BAR1
        if (tid < 8) {
            u64 s0 = 0ull, s1 = 0ull, s2 = 0ull, s3 = 0ull;
            #pragma unroll
            for (int w = 0; w < 8; w++) {
                s0 = fadd2(s0, ppu[(4 * w + 0) * 8 + tid]);
                s1 = fadd2(s1, ppu[(4 * w + 1) * 8 + tid]);
                s2 = fadd2(s2, ppu[(4 * w + 2) * 8 + tid]);
                s3 = fadd2(s3, ppu[(4 * w + 3) * 8 + tid]);
            }
            u64 s = fadd2(fadd2(s0, s1), fadd2(s2, s3));
            float lo, hi; upk2(s, lo, hi);
            *(float2*)(Psh + 2 * tid) = make_float2(lo, hi);
        }
        __syncthreads();                               // BAR2
        // ---- stage 1: A[n][e] = sum_d P[d] * g4[d][n][e] ----
        if (tid < 256) {
            float s = 0.f;
            #pragma unroll
            for (int d = 0; d < 16; d++)
                s = fmaf(Psh[d], g4sh[d * 256 + tid], s);
            Ash[tid] = s;
        }
        __syncthreads();                               // BAR3
        // ---- stage 2 (packed over e-pairs) ----
        u64 a0 = pk2(ihg.x, 0.f);
        u64 a1 = pk2(ihg.y, 0.f);
        u64 a2 = pk2(ihg.z, 0.f);
        u64 a3 = pk2(ihg.w, 0.f);
        {
            const u64* Ar0 = (const u64*)(Ash + (0 * 4 + nb) * 16);
            const u64* Ar1 = (const u64*)(Ash + (1 * 4 + nb) * 16);
            const u64* Ar2 = (const u64*)(Ash + (2 * 4 + nb) * 16);
            const u64* Ar3 = (const u64*)(Ash + (3 * 4 + nb) * 16);
            #pragma unroll
            for (int i = 0; i < 8; i++) {
                a0 = ffma2(Ar0[i], Gp[i], a0);
                a1 = ffma2(Ar1[i], Gp[i], a1);
                a2 = ffma2(Ar2[i], Gp[i], a2);
                a3 = ffma2(Ar3[i], Gp[i], a3);
            }
        }
        float l0, h0_, l1, h1_, l2, h2_, l3, h3_;
        upk2(a0, l0, h0_); upk2(a1, l1, h1_);
        upk2(a2, l2, h2_); upk2(a3, l3, h3_);
        float gi = l0 + h0_, gf = l1 + h1_, gg = l2 + h2_, go = l3 + h3_;

        // ---- LSTM cell ----
        float si = sigmoidf(gi);
        float sf = sigmoidf(gf);
        float tg = tanhf_(gg);
        float so = sigmoidf(go);
        c = sf * c + si * tg;
        h = so * tanhf_(c);

        outb[(size_t)t * DH + tid] = h;
    }

    // final (h, c) appended after output tensor
    float* hc = out + (size_t)BB * TT * DH;
    hc[b * DH + tid] = h;
    hc[(size_t)BB * DH + b * DH + tid] = c;
}

// ---------------- launcher -------------------------------------------------
extern "C" void kernel_launch(void* const* d_in, const int* in_sizes, int n_in,
                              void* d_out, int out_size)
{
    const float* x    = (const float*)d_in[0];
    const float* ih1  = (const float*)d_in[1];
    const float* ih2  = (const float*)d_in[2];
    const float* ih3  = (const float*)d_in[3];
    const float* ih4  = (const float*)d_in[4];
    const float* ih5  = (const float*)d_in[5];
    const float* ih6  = (const float*)d_in[6];
    const float* hh1  = (const float*)d_in[7];
    const float* hh2  = (const float*)d_in[8];
    const float* hh3  = (const float*)d_in[9];
    const float* hh4  = (const float*)d_in[10];
    const float* hh5  = (const float*)d_in[11];
    const float* hh6  = (const float*)d_in[12];
    const float* bih  = (const float*)d_in[13];
    const float* bhh  = (const float*)d_in[14];
    float* out = (float*)d_out;

    k_build<<<2, 1024>>>(ih1, ih2, ih3, ih5, ih6,
                         hh1, hh2, hh3, hh5, hh6, bih, bhh);
    k_pre<<<BB * TT, 256>>>(x, ih4);
    k_rec<<<BB, 1024>>>(hh4, out);
}